// round 3
// baseline (speedup 1.0000x reference)
#include <cuda_runtime.h>
#include <cuda_bf16.h>
#include <cstdint>

// ---------------------------------------------------------------------------
// ContextLayer: z = sigmoid((concat(x1,x2)@W1+b)@We); r = tanh(z@Wr)
//               scan: c_t = softmax(c_{t-1}@Wf) * c_{t-1} + r_t * z_t
// ---------------------------------------------------------------------------

#define TT   32768
#define SZ   512
#define HIDN 768
#define DIN  1024

#define CLUSTER_N    8
#define COLS_PER_CTA 64            // SZ / CLUSTER_N
#define SCAN_THREADS 256

// scan smem layout (bytes)
#define SW_BYTES   (COLS_PER_CTA * SZ * 2)   // 65536: bf16 W slice, [col][i]
#define C_OFF      (SW_BYTES)                // 512 f32 c vector
#define YB_OFF     (C_OFF + SZ * 4)          // 2 x 512 f32 y mailbox (ping/pong)
#define YM_OFF     (YB_OFF + 2 * SZ * 4)     // 64 f32 local y chunk
#define RM_OFF     (YM_OFF + COLS_PER_CTA * 4)
#define RS_OFF     (RM_OFF + 32)
#define SMEM_SCAN  (RS_OFF + 32)             // 72000 bytes

// scratch (static device arrays: no allocation at kernel_launch time)
__device__ float         g_h[(size_t)TT * HIDN];   // 96 MB
__device__ float         g_z[(size_t)TT * SZ];     // 64 MB
__device__ float         g_r[TT];
__device__ __nv_bfloat16 g_wfT[SZ * SZ];           // W_forget, column-major bf16

// ---------------------------------------------------------------------------
// helpers
// ---------------------------------------------------------------------------
__device__ __forceinline__ uint32_t smem_u32(const void* p) {
    uint32_t a;
    asm("{ .reg .u64 t; cvta.to.shared.u64 t, %1; cvt.u32.u64 %0, t; }"
        : "=r"(a) : "l"(p));
    return a;
}
__device__ __forceinline__ float bf_lo(uint32_t u) { return __uint_as_float(u << 16); }
// hi bf16 reinterpreted with low-half garbage mantissa bits: rel err < 2^-8,
// only perturbs the softmax gate which scales a ~1% memory term. Safe.
__device__ __forceinline__ float bf_hi(uint32_t u) { return __uint_as_float(u); }

#define CLUSTER_SYNC() do { \
    asm volatile("barrier.cluster.arrive.aligned;" ::: "memory"); \
    asm volatile("barrier.cluster.wait.aligned;"   ::: "memory"); } while (0)

// ---------------------------------------------------------------------------
// GEMM1: g_h = concat(x1,x2) @ W_linear + b     (M=32768, K=1024, N=768)
// 128x128 tile, BK=8, 256 threads, 8x8 microtile
// ---------------------------------------------------------------------------
__global__ __launch_bounds__(256) void gemm1_kernel(
    const float* __restrict__ x1, const float* __restrict__ x2,
    const float* __restrict__ W, const float* __restrict__ bias)
{
    __shared__ float As[8][128];
    __shared__ float Bs[8][128];
    const int tid  = threadIdx.x;
    const int bm   = blockIdx.y << 7;
    const int bn   = blockIdx.x << 7;
    const int lrow = tid >> 1;
    const int lkq  = (tid & 1) << 2;
    const int brow = tid >> 5;
    const int bcol = (tid & 31) << 2;
    const int tm   = (tid >> 4) << 3;
    const int tn   = (tid & 15) << 3;

    float acc[8][8];
#pragma unroll
    for (int i = 0; i < 8; ++i)
#pragma unroll
        for (int j = 0; j < 8; ++j) acc[i][j] = 0.f;

    for (int k0 = 0; k0 < DIN; k0 += 8) {
        const int gk = k0 + lkq;  // never straddles the 512 boundary (8 | 512)
        const float* asrc = (gk < 512)
            ? (x1 + (size_t)(bm + lrow) * 512 + gk)
            : (x2 + (size_t)(bm + lrow) * 512 + (gk - 512));
        const float4 av = *(const float4*)asrc;
        const float4 bv = *(const float4*)(W + (size_t)(k0 + brow) * HIDN + bn + bcol);
        __syncthreads();
        As[lkq + 0][lrow] = av.x;
        As[lkq + 1][lrow] = av.y;
        As[lkq + 2][lrow] = av.z;
        As[lkq + 3][lrow] = av.w;
        *(float4*)&Bs[brow][bcol] = bv;
        __syncthreads();
#pragma unroll
        for (int kk = 0; kk < 8; ++kk) {
            float a[8], b[8];
            *(float4*)&a[0] = *(const float4*)&As[kk][tm];
            *(float4*)&a[4] = *(const float4*)&As[kk][tm + 4];
            *(float4*)&b[0] = *(const float4*)&Bs[kk][tn];
            *(float4*)&b[4] = *(const float4*)&Bs[kk][tn + 4];
#pragma unroll
            for (int i = 0; i < 8; ++i)
#pragma unroll
                for (int j = 0; j < 8; ++j)
                    acc[i][j] = fmaf(a[i], b[j], acc[i][j]);
        }
    }
    float bb[8];
    *(float4*)&bb[0] = *(const float4*)(bias + bn + tn);
    *(float4*)&bb[4] = *(const float4*)(bias + bn + tn + 4);
#pragma unroll
    for (int i = 0; i < 8; ++i) {
        float4 o0, o1;
        o0.x = acc[i][0] + bb[0]; o0.y = acc[i][1] + bb[1];
        o0.z = acc[i][2] + bb[2]; o0.w = acc[i][3] + bb[3];
        o1.x = acc[i][4] + bb[4]; o1.y = acc[i][5] + bb[5];
        o1.z = acc[i][6] + bb[6]; o1.w = acc[i][7] + bb[7];
        float* dst = g_h + (size_t)(bm + tm + i) * HIDN + bn + tn;
        *(float4*)dst       = o0;
        *(float4*)(dst + 4) = o1;
    }
}

// ---------------------------------------------------------------------------
// GEMM2: g_z = sigmoid(g_h @ W_embed)           (M=32768, K=768, N=512)
// ---------------------------------------------------------------------------
__global__ __launch_bounds__(256) void gemm2_kernel(const float* __restrict__ W)
{
    __shared__ float As[8][128];
    __shared__ float Bs[8][128];
    const int tid  = threadIdx.x;
    const int bm   = blockIdx.y << 7;
    const int bn   = blockIdx.x << 7;
    const int lrow = tid >> 1;
    const int lkq  = (tid & 1) << 2;
    const int brow = tid >> 5;
    const int bcol = (tid & 31) << 2;
    const int tm   = (tid >> 4) << 3;
    const int tn   = (tid & 15) << 3;

    float acc[8][8];
#pragma unroll
    for (int i = 0; i < 8; ++i)
#pragma unroll
        for (int j = 0; j < 8; ++j) acc[i][j] = 0.f;

    for (int k0 = 0; k0 < HIDN; k0 += 8) {
        const float4 av = *(const float4*)(g_h + (size_t)(bm + lrow) * HIDN + k0 + lkq);
        const float4 bv = *(const float4*)(W + (size_t)(k0 + brow) * SZ + bn + bcol);
        __syncthreads();
        As[lkq + 0][lrow] = av.x;
        As[lkq + 1][lrow] = av.y;
        As[lkq + 2][lrow] = av.z;
        As[lkq + 3][lrow] = av.w;
        *(float4*)&Bs[brow][bcol] = bv;
        __syncthreads();
#pragma unroll
        for (int kk = 0; kk < 8; ++kk) {
            float a[8], b[8];
            *(float4*)&a[0] = *(const float4*)&As[kk][tm];
            *(float4*)&a[4] = *(const float4*)&As[kk][tm + 4];
            *(float4*)&b[0] = *(const float4*)&Bs[kk][tn];
            *(float4*)&b[4] = *(const float4*)&Bs[kk][tn + 4];
#pragma unroll
            for (int i = 0; i < 8; ++i)
#pragma unroll
                for (int j = 0; j < 8; ++j)
                    acc[i][j] = fmaf(a[i], b[j], acc[i][j]);
        }
    }
#pragma unroll
    for (int i = 0; i < 8; ++i) {
        float o[8];
#pragma unroll
        for (int j = 0; j < 8; ++j)
            o[j] = 1.0f / (1.0f + __expf(-acc[i][j]));
        float* dst = g_z + (size_t)(bm + tm + i) * SZ + bn + tn;
        *(float4*)dst       = *(float4*)&o[0];
        *(float4*)(dst + 4) = *(float4*)&o[4];
    }
}

// ---------------------------------------------------------------------------
// rate: g_r[t] = tanh(dot(g_z[t,:], W_rate))    (one warp per row)
// ---------------------------------------------------------------------------
__global__ __launch_bounds__(128) void rate_kernel(const float* __restrict__ Wr)
{
    __shared__ float wr[SZ];
    const int tid = threadIdx.x;
    for (int i = tid; i < SZ; i += 128) wr[i] = Wr[i];
    __syncthreads();
    const int row  = blockIdx.x * 4 + (tid >> 5);
    const int lane = tid & 31;
    const float* zr = g_z + (size_t)row * SZ;
    float s = 0.f;
#pragma unroll
    for (int i = 0; i < 16; ++i) s = fmaf(zr[lane + 32 * i], wr[lane + 32 * i], s);
#pragma unroll
    for (int off = 16; off > 0; off >>= 1) s += __shfl_xor_sync(0xffffffffu, s, off);
    if (lane == 0) g_r[row] = tanhf(s);
}

// ---------------------------------------------------------------------------
// pack W_forget -> column-major bf16
// ---------------------------------------------------------------------------
__global__ __launch_bounds__(256) void pack_wf_kernel(const float* __restrict__ Wf)
{
    const int idx = blockIdx.x * 256 + threadIdx.x;
    if (idx < SZ * SZ) {
        const int i = idx >> 9, j = idx & 511;
        g_wfT[j * SZ + i] = __float2bfloat16(Wf[idx]);
    }
}

// ---------------------------------------------------------------------------
// scan: cluster of 8 CTAs, one barrier per step.
//   CTA k owns 64 columns of W_forget (bf16, smem-resident).
//   step: local matvec -> broadcast 64 y's to all CTAs (DSMEM push) ->
//         cluster barrier -> every CTA does the full softmax + c-update
//         locally (redundant) -> each CTA writes its 64-col chunk of ys[t].
// ---------------------------------------------------------------------------
__global__ void __cluster_dims__(CLUSTER_N, 1, 1) __launch_bounds__(SCAN_THREADS, 1)
scan_kernel(const float* __restrict__ ctx0, float* __restrict__ out)
{
    extern __shared__ unsigned char sm[];
    unsigned char* swb = sm;                       // bf16 W slice [col][i]
    float* c    = (float*)(sm + C_OFF);
    float* yb   = (float*)(sm + YB_OFF);
    float* ym   = (float*)(sm + YM_OFF);
    float* redm = (float*)(sm + RM_OFF);
    float* reds = (float*)(sm + RS_OFF);

    const int tid  = threadIdx.x;
    const int rank = blockIdx.x;                   // grid == one cluster
    const int w    = tid >> 5;
    const int l    = tid & 31;

    // load my 64-column bf16 W slice (64 KB)
    {
        const float4* src = (const float4*)(g_wfT + (size_t)rank * COLS_PER_CTA * SZ);
        float4* dst = (float4*)swb;
        for (int i = tid; i < SW_BYTES / 16; i += SCAN_THREADS) dst[i] = src[i];
    }
    c[tid]       = ctx0[tid];
    c[tid + 256] = ctx0[tid + 256];
    const uint32_t yb_u32 = smem_u32(yb);
    __syncthreads();
    CLUSTER_SYNC();

    for (int t = 0; t < TT; ++t) {
        // prefetch z_t, r_t early (used after the barrier; latency hidden)
        const float z0 = __ldg(&g_z[(size_t)t * SZ + tid]);
        const float z1 = __ldg(&g_z[(size_t)t * SZ + tid + 256]);
        const float rt = __ldg(&g_r[t]);

        // ---- matvec: y[col] = sum_i c[i] * W[i][col], lanes split i ----
        float ca[8], cb[8];
        *(float4*)&ca[0] = *(const float4*)(c + l * 8);
        *(float4*)&ca[4] = *(const float4*)(c + l * 8 + 4);
        *(float4*)&cb[0] = *(const float4*)(c + 256 + l * 8);
        *(float4*)&cb[4] = *(const float4*)(c + 256 + l * 8 + 4);
#pragma unroll
        for (int jj = 0; jj < 8; ++jj) {
            const int col = (w << 3) + jj;
            const uint4 wa = *(const uint4*)(swb + col * 1024 + (l << 4));
            const uint4 wbv = *(const uint4*)(swb + col * 1024 + 512 + (l << 4));
            float p;
            p = bf_lo(wa.x) * ca[0];
            p = fmaf(bf_hi(wa.x), ca[1], p);
            p = fmaf(bf_lo(wa.y), ca[2], p);
            p = fmaf(bf_hi(wa.y), ca[3], p);
            p = fmaf(bf_lo(wa.z), ca[4], p);
            p = fmaf(bf_hi(wa.z), ca[5], p);
            p = fmaf(bf_lo(wa.w), ca[6], p);
            p = fmaf(bf_hi(wa.w), ca[7], p);
            p = fmaf(bf_lo(wbv.x), cb[0], p);
            p = fmaf(bf_hi(wbv.x), cb[1], p);
            p = fmaf(bf_lo(wbv.y), cb[2], p);
            p = fmaf(bf_hi(wbv.y), cb[3], p);
            p = fmaf(bf_lo(wbv.z), cb[4], p);
            p = fmaf(bf_hi(wbv.z), cb[5], p);
            p = fmaf(bf_lo(wbv.w), cb[6], p);
            p = fmaf(bf_hi(wbv.w), cb[7], p);
#pragma unroll
            for (int off = 16; off > 0; off >>= 1)
                p += __shfl_xor_sync(0xffffffffu, p, off);
            if (l == 0) ym[col] = p;
        }
        __syncthreads();

        // ---- push my 64 y values into every CTA's mailbox (incl. self) ----
        {
            const int v = tid & 63;
            const float val = ym[v];
            const uint32_t laddr =
                yb_u32 + (uint32_t)((((t & 1) << 9) + (rank << 6) + v) * 4);
            int tgt = tid >> 6;
#pragma unroll
            for (int rep = 0; rep < 2; ++rep) {
                uint32_t raddr;
                asm volatile("mapa.shared::cluster.u32 %0, %1, %2;"
                             : "=r"(raddr) : "r"(laddr), "r"(tgt));
                asm volatile("st.shared::cluster.f32 [%0], %1;"
                             :: "r"(raddr), "f"(val) : "memory");
                tgt += 4;
            }
        }
        CLUSTER_SYNC();

        // ---- full softmax + c update (redundant in every CTA) ----
        const float* y = yb + ((t & 1) << 9);
        const float y0 = y[tid], y1 = y[tid + 256];
        float m = fmaxf(y0, y1);
#pragma unroll
        for (int off = 16; off > 0; off >>= 1)
            m = fmaxf(m, __shfl_xor_sync(0xffffffffu, m, off));
        if (l == 0) redm[w] = m;
        __syncthreads();
        m = redm[0];
#pragma unroll
        for (int k = 1; k < 8; ++k) m = fmaxf(m, redm[k]);

        const float e0 = exp2f((y0 - m) * 1.4426950408889634f);
        const float e1 = exp2f((y1 - m) * 1.4426950408889634f);
        float s = e0 + e1;
#pragma unroll
        for (int off = 16; off > 0; off >>= 1)
            s += __shfl_xor_sync(0xffffffffu, s, off);
        if (l == 0) reds[w] = s;
        __syncthreads();
        s = reds[0];
#pragma unroll
        for (int k = 1; k < 8; ++k) s += reds[k];
        const float inv = __fdividef(1.0f, s);

        const float n0 = fmaf(e0 * inv, c[tid], rt * z0);
        const float n1 = fmaf(e1 * inv, c[tid + 256], rt * z1);
        c[tid]       = n0;
        c[tid + 256] = n1;
        if ((tid >> 6) == rank)           out[(size_t)t * SZ + tid]       = n0;
        if (((tid + 256) >> 6) == rank)   out[(size_t)t * SZ + tid + 256] = n1;
        __syncthreads();   // c updated before next step's matvec reads it
    }
}

// ---------------------------------------------------------------------------
// launch
// ---------------------------------------------------------------------------
extern "C" void kernel_launch(void* const* d_in, const int* in_sizes, int n_in,
                              void* d_out, int out_size)
{
    const float* x1   = (const float*)d_in[0];
    const float* x2   = (const float*)d_in[1];
    const float* ctx0 = (const float*)d_in[2];
    const float* Wl   = (const float*)d_in[3];
    const float* bl   = (const float*)d_in[4];
    const float* We   = (const float*)d_in[5];
    const float* Wr   = (const float*)d_in[6];
    const float* Wf   = (const float*)d_in[7];
    float* out = (float*)d_out;

    cudaFuncSetAttribute(scan_kernel, cudaFuncAttributeMaxDynamicSharedMemorySize,
                         SMEM_SCAN);

    gemm1_kernel<<<dim3(HIDN / 128, TT / 128), 256>>>(x1, x2, Wl, bl);
    gemm2_kernel<<<dim3(SZ / 128, TT / 128), 256>>>(We);
    rate_kernel<<<TT / 4, 128>>>(Wr);
    pack_wf_kernel<<<(SZ * SZ) / 256, 256>>>(Wf);
    scan_kernel<<<CLUSTER_N, SCAN_THREADS, SMEM_SCAN>>>(ctx0, out);
}

// round 4
// speedup vs baseline: 2.2232x; 2.2232x over previous
#include <cuda_runtime.h>
#include <cuda_bf16.h>
#include <cstdint>

// ---------------------------------------------------------------------------
// ContextLayer: z = sigmoid((concat(x1,x2)@W1+b)@We); r = tanh(z@Wr)
//               scan: c_t = softmax(c_{t-1}@Wf) * c_{t-1} + r_t * z_t
// ---------------------------------------------------------------------------

#define TT   32768
#define SZ   512
#define HIDN 768
#define DIN  1024

#define CLUSTER_N 8
#define LOG2E 1.4426950408889634f

// scratch (static device arrays: no allocation at kernel_launch time)
__device__ float g_h[(size_t)TT * HIDN];   // 96 MB
__device__ float g_z[(size_t)TT * SZ];     // 64 MB
__device__ float g_r[TT];

// ---------------------------------------------------------------------------
// helpers
// ---------------------------------------------------------------------------
__device__ __forceinline__ uint32_t smem_u32(const void* p) {
    uint32_t a;
    asm("{ .reg .u64 t; cvta.to.shared.u64 t, %1; cvt.u32.u64 %0, t; }"
        : "=r"(a) : "l"(p));
    return a;
}

#define PACK2(dst, lo, hi) \
    asm("mov.b64 %0, {%1, %2};" : "=l"(dst) : "f"(lo), "f"(hi))
#define UNPACK2(lo, hi, src) \
    asm("mov.b64 {%0, %1}, %2;" : "=f"(lo), "=f"(hi) : "l"(src))
#define MUL2(d, a, b) \
    asm("mul.rn.f32x2 %0, %1, %2;" : "=l"(d) : "l"(a), "l"(b))
#define FMA2(d, a, b, c) \
    asm("fma.rn.f32x2 %0, %1, %2, %3;" : "=l"(d) : "l"(a), "l"(b), "l"(c))
#define FMA2ACC(d, a, b) \
    asm("fma.rn.f32x2 %0, %1, %2, %0;" : "+l"(d) : "l"(a), "l"(b))

#define CLUSTER_SYNC() do { \
    asm volatile("barrier.cluster.arrive.aligned;" ::: "memory"); \
    asm volatile("barrier.cluster.wait.aligned;"   ::: "memory"); } while (0)

// wait with cluster-scope acquire (incoming data are remote st.async)
#define WAIT_PARITY_CLUSTER(addr, ph) do {                                     \
    uint32_t _done;                                                            \
    asm volatile(                                                              \
        "{\n\t.reg .pred p;\n\t"                                               \
        "mbarrier.try_wait.parity.acquire.cluster.shared::cta.b64 p, [%1], %2;\n\t" \
        "selp.b32 %0, 1, 0, p;\n\t}"                                           \
        : "=r"(_done) : "r"(addr), "r"(ph) : "memory");                        \
    while (!_done) {                                                           \
        asm volatile(                                                          \
            "{\n\t.reg .pred p;\n\t"                                           \
            "mbarrier.try_wait.parity.acquire.cluster.shared::cta.b64 p, [%1], %2, 0x989680;\n\t" \
            "selp.b32 %0, 1, 0, p;\n\t}"                                       \
            : "=r"(_done) : "r"(addr), "r"(ph) : "memory");                    \
    } } while (0)

// ---------------------------------------------------------------------------
// GEMM1: g_h = concat(x1,x2) @ W_linear + b     (M=32768, K=1024, N=768)
// ---------------------------------------------------------------------------
__global__ __launch_bounds__(256) void gemm1_kernel(
    const float* __restrict__ x1, const float* __restrict__ x2,
    const float* __restrict__ W, const float* __restrict__ bias)
{
    __shared__ float As[8][128];
    __shared__ float Bs[8][128];
    const int tid  = threadIdx.x;
    const int bm   = blockIdx.y << 7;
    const int bn   = blockIdx.x << 7;
    const int lrow = tid >> 1;
    const int lkq  = (tid & 1) << 2;
    const int brow = tid >> 5;
    const int bcol = (tid & 31) << 2;
    const int tm   = (tid >> 4) << 3;
    const int tn   = (tid & 15) << 3;

    float acc[8][8];
#pragma unroll
    for (int i = 0; i < 8; ++i)
#pragma unroll
        for (int j = 0; j < 8; ++j) acc[i][j] = 0.f;

    for (int k0 = 0; k0 < DIN; k0 += 8) {
        const int gk = k0 + lkq;
        const float* asrc = (gk < 512)
            ? (x1 + (size_t)(bm + lrow) * 512 + gk)
            : (x2 + (size_t)(bm + lrow) * 512 + (gk - 512));
        const float4 av = *(const float4*)asrc;
        const float4 bv = *(const float4*)(W + (size_t)(k0 + brow) * HIDN + bn + bcol);
        __syncthreads();
        As[lkq + 0][lrow] = av.x;
        As[lkq + 1][lrow] = av.y;
        As[lkq + 2][lrow] = av.z;
        As[lkq + 3][lrow] = av.w;
        *(float4*)&Bs[brow][bcol] = bv;
        __syncthreads();
#pragma unroll
        for (int kk = 0; kk < 8; ++kk) {
            float a[8], b[8];
            *(float4*)&a[0] = *(const float4*)&As[kk][tm];
            *(float4*)&a[4] = *(const float4*)&As[kk][tm + 4];
            *(float4*)&b[0] = *(const float4*)&Bs[kk][tn];
            *(float4*)&b[4] = *(const float4*)&Bs[kk][tn + 4];
#pragma unroll
            for (int i = 0; i < 8; ++i)
#pragma unroll
                for (int j = 0; j < 8; ++j)
                    acc[i][j] = fmaf(a[i], b[j], acc[i][j]);
        }
    }
    float bb[8];
    *(float4*)&bb[0] = *(const float4*)(bias + bn + tn);
    *(float4*)&bb[4] = *(const float4*)(bias + bn + tn + 4);
#pragma unroll
    for (int i = 0; i < 8; ++i) {
        float4 o0, o1;
        o0.x = acc[i][0] + bb[0]; o0.y = acc[i][1] + bb[1];
        o0.z = acc[i][2] + bb[2]; o0.w = acc[i][3] + bb[3];
        o1.x = acc[i][4] + bb[4]; o1.y = acc[i][5] + bb[5];
        o1.z = acc[i][6] + bb[6]; o1.w = acc[i][7] + bb[7];
        float* dst = g_h + (size_t)(bm + tm + i) * HIDN + bn + tn;
        *(float4*)dst       = o0;
        *(float4*)(dst + 4) = o1;
    }
}

// ---------------------------------------------------------------------------
// GEMM2: g_z = sigmoid(g_h @ W_embed)           (M=32768, K=768, N=512)
// ---------------------------------------------------------------------------
__global__ __launch_bounds__(256) void gemm2_kernel(const float* __restrict__ W)
{
    __shared__ float As[8][128];
    __shared__ float Bs[8][128];
    const int tid  = threadIdx.x;
    const int bm   = blockIdx.y << 7;
    const int bn   = blockIdx.x << 7;
    const int lrow = tid >> 1;
    const int lkq  = (tid & 1) << 2;
    const int brow = tid >> 5;
    const int bcol = (tid & 31) << 2;
    const int tm   = (tid >> 4) << 3;
    const int tn   = (tid & 15) << 3;

    float acc[8][8];
#pragma unroll
    for (int i = 0; i < 8; ++i)
#pragma unroll
        for (int j = 0; j < 8; ++j) acc[i][j] = 0.f;

    for (int k0 = 0; k0 < HIDN; k0 += 8) {
        const float4 av = *(const float4*)(g_h + (size_t)(bm + lrow) * HIDN + k0 + lkq);
        const float4 bv = *(const float4*)(W + (size_t)(k0 + brow) * SZ + bn + bcol);
        __syncthreads();
        As[lkq + 0][lrow] = av.x;
        As[lkq + 1][lrow] = av.y;
        As[lkq + 2][lrow] = av.z;
        As[lkq + 3][lrow] = av.w;
        *(float4*)&Bs[brow][bcol] = bv;
        __syncthreads();
#pragma unroll
        for (int kk = 0; kk < 8; ++kk) {
            float a[8], b[8];
            *(float4*)&a[0] = *(const float4*)&As[kk][tm];
            *(float4*)&a[4] = *(const float4*)&As[kk][tm + 4];
            *(float4*)&b[0] = *(const float4*)&Bs[kk][tn];
            *(float4*)&b[4] = *(const float4*)&Bs[kk][tn + 4];
#pragma unroll
            for (int i = 0; i < 8; ++i)
#pragma unroll
                for (int j = 0; j < 8; ++j)
                    acc[i][j] = fmaf(a[i], b[j], acc[i][j]);
        }
    }
#pragma unroll
    for (int i = 0; i < 8; ++i) {
        float o[8];
#pragma unroll
        for (int j = 0; j < 8; ++j)
            o[j] = 1.0f / (1.0f + __expf(-acc[i][j]));
        float* dst = g_z + (size_t)(bm + tm + i) * SZ + bn + tn;
        *(float4*)dst       = *(float4*)&o[0];
        *(float4*)(dst + 4) = *(float4*)&o[4];
    }
}

// ---------------------------------------------------------------------------
// rate: g_r[t] = tanh(dot(g_z[t,:], W_rate))    (one warp per row)
// ---------------------------------------------------------------------------
__global__ __launch_bounds__(128) void rate_kernel(const float* __restrict__ Wr)
{
    __shared__ float wr[SZ];
    const int tid = threadIdx.x;
    for (int i = tid; i < SZ; i += 128) wr[i] = Wr[i];
    __syncthreads();
    const int row  = blockIdx.x * 4 + (tid >> 5);
    const int lane = tid & 31;
    const float* zr = g_z + (size_t)row * SZ;
    float s = 0.f;
#pragma unroll
    for (int i = 0; i < 16; ++i) s = fmaf(zr[lane + 32 * i], wr[lane + 32 * i], s);
#pragma unroll
    for (int off = 16; off > 0; off >>= 1) s += __shfl_xor_sync(0xffffffffu, s, off);
    if (lane == 0) g_r[row] = tanhf(s);
}

// ---------------------------------------------------------------------------
// scan: cluster of 8 CTAs. W_forget fp32 REGISTER-resident (f32x2 pairs),
// c register-resident (warp-replicated slices). Per step:
//   matvec (fma.f32x2) -> warp butterfly -> st.async y-broadcast with
//   mbarrier complete_tx -> try_wait (no cluster.sync, no L1 flush) ->
//   canonical exp stage (1 syncthreads) -> packed slice update.
// ---------------------------------------------------------------------------
__global__ void __cluster_dims__(CLUSTER_N, 1, 1) __launch_bounds__(256, 1)
scan_kernel(const float* __restrict__ Wf, const float* __restrict__ ctx0,
            float* __restrict__ out)
{
    __shared__ __align__(16) float yb[2][SZ];     // y mailbox (ping/pong)
    __shared__ __align__(16) float eb[2][SZ];     // exp stage  (ping/pong)
    __shared__ float reds[2][8];
    __shared__ __align__(8) unsigned long long mbar[2];

    const int tid  = threadIdx.x;
    const int w    = tid >> 5;
    const int l    = tid & 31;
    const int rank = (int)blockIdx.x;              // grid == one cluster

    // ---- W slice into registers: 8 cols x 8 f32x2 pairs per thread ----
    // col j = 64*rank + 8*w + jj ; pair k<4: i = 8l+2k ; k>=4: i = 256+8l+2(k-4)
    unsigned long long wp[8][8];
#pragma unroll
    for (int jj = 0; jj < 8; ++jj) {
        const int col = rank * 64 + w * 8 + jj;
#pragma unroll
        for (int k = 0; k < 8; ++k) {
            const int i0 = (k < 4) ? (8 * l + 2 * k) : (256 + 8 * l + 2 * (k - 4));
            const float f0 = Wf[(size_t)i0 * SZ + col];
            const float f1 = Wf[(size_t)(i0 + 1) * SZ + col];
            PACK2(wp[jj][k], f0, f1);
        }
    }
    // ---- c slice pairs ----
    unsigned long long cp[8];
#pragma unroll
    for (int k = 0; k < 8; ++k) {
        const int i0 = (k < 4) ? (8 * l + 2 * k) : (256 + 8 * l + 2 * (k - 4));
        PACK2(cp[k], ctx0[i0], ctx0[i0 + 1]);
    }

    const uint32_t yb_base = smem_u32(&yb[0][0]);
    const uint32_t mb_base = smem_u32(&mbar[0]);
    if (tid == 0) {
        asm volatile("mbarrier.init.shared.b64 [%0], %1;" :: "r"(mb_base), "r"(1u) : "memory");
        asm volatile("mbarrier.init.shared.b64 [%0], %1;" :: "r"(mb_base + 8), "r"(1u) : "memory");
    }
    __syncthreads();
    CLUSTER_SYNC();   // mbarriers visible cluster-wide before any st.async

    const int mycol = rank * 64 + w * 8 + (l & 7);   // col this lane pushes

    for (int t = 0; t < TT; ++t) {
        const int      buf   = t & 1;
        const uint32_t phase = (uint32_t)((t >> 1) & 1);

        // prefetch z slice + r_t (consumed after the wait; latency hidden)
        const float* zrow = g_z + (size_t)t * SZ;
        const float4 zv0 = __ldg((const float4*)(zrow + 8 * l));
        const float4 zv1 = __ldg((const float4*)(zrow + 8 * l + 4));
        const float4 zv2 = __ldg((const float4*)(zrow + 256 + 8 * l));
        const float4 zv3 = __ldg((const float4*)(zrow + 256 + 8 * l + 4));
        const float  rt  = __ldg(&g_r[t]);

        // post expected transaction bytes for this step's mailbox
        if (tid == 0)
            asm volatile("mbarrier.arrive.expect_tx.shared.b64 _, [%0], %1;"
                         :: "r"(mb_base + buf * 8), "r"(2048u) : "memory");

        // ---- matvec: y[col] = sum_i c[i] * W[i][col] (packed f32x2) ----
        float y[8];
#pragma unroll
        for (int jj = 0; jj < 8; ++jj) {
            unsigned long long acc;
            MUL2(acc, wp[jj][0], cp[0]);
#pragma unroll
            for (int k = 1; k < 8; ++k) FMA2ACC(acc, wp[jj][k], cp[k]);
            float plo, phi;
            UNPACK2(plo, phi, acc);
            float p = plo + phi;
#pragma unroll
            for (int off = 16; off > 0; off >>= 1)
                p += __shfl_xor_sync(0xffffffffu, p, off);
            y[jj] = p;           // all lanes hold col sum
        }

        // ---- push: lane handles (col = l&7, tgt = l>>3) and (tgt+4) ----
        {
            const float v = (l & 4)
                ? ((l & 2) ? ((l & 1) ? y[7] : y[6]) : ((l & 1) ? y[5] : y[4]))
                : ((l & 2) ? ((l & 1) ? y[3] : y[2]) : ((l & 1) ? y[1] : y[0]));
            const uint32_t uv    = __float_as_uint(v);
            const uint32_t laddr = yb_base + (uint32_t)(buf * 2048 + mycol * 4);
            const uint32_t lmbar = mb_base + (uint32_t)(buf * 8);
#pragma unroll
            for (int rep = 0; rep < 2; ++rep) {
                const int tgt = (l >> 3) + rep * 4;
                uint32_t ra, rm;
                asm volatile("mapa.shared::cluster.u32 %0, %1, %2;"
                             : "=r"(ra) : "r"(laddr), "r"(tgt));
                asm volatile("mapa.shared::cluster.u32 %0, %1, %2;"
                             : "=r"(rm) : "r"(lmbar), "r"(tgt));
                asm volatile(
                    "st.async.shared::cluster.mbarrier::complete_tx::bytes.b32 [%0], %1, [%2];"
                    :: "r"(ra), "r"(uv), "r"(rm) : "memory");
            }
        }

        WAIT_PARITY_CLUSTER(mb_base + buf * 8, phase);

        // ---- exp computed once per CTA (canonical), staged via smem ----
        const float y0 = yb[buf][tid], y1 = yb[buf][tid + 256];
        const float e0 = exp2f(y0 * LOG2E);          // |y| small: no max needed
        const float e1 = exp2f(y1 * LOG2E);
        float s = e0 + e1;
#pragma unroll
        for (int off = 16; off > 0; off >>= 1)
            s += __shfl_xor_sync(0xffffffffu, s, off);
        eb[buf][tid]       = e0;
        eb[buf][tid + 256] = e1;
        if (l == 0) reds[buf][w] = s;
        __syncthreads();

        float tot = reds[buf][0];
#pragma unroll
        for (int k = 1; k < 8; ++k) tot += reds[buf][k];
        const float inv = __fdividef(1.0f, tot);

        // ---- packed slice update: c = (e*inv)*c + rt*z ----
        unsigned long long invp, rtp;
        PACK2(invp, inv, inv);
        PACK2(rtp, rt, rt);
        const float4 ev0 = *(const float4*)&eb[buf][8 * l];
        const float4 ev1 = *(const float4*)&eb[buf][8 * l + 4];
        const float4 ev2 = *(const float4*)&eb[buf][256 + 8 * l];
        const float4 ev3 = *(const float4*)&eb[buf][256 + 8 * l + 4];
        unsigned long long ep[8], zp[8];
        PACK2(ep[0], ev0.x, ev0.y); PACK2(ep[1], ev0.z, ev0.w);
        PACK2(ep[2], ev1.x, ev1.y); PACK2(ep[3], ev1.z, ev1.w);
        PACK2(ep[4], ev2.x, ev2.y); PACK2(ep[5], ev2.z, ev2.w);
        PACK2(ep[6], ev3.x, ev3.y); PACK2(ep[7], ev3.z, ev3.w);
        PACK2(zp[0], zv0.x, zv0.y); PACK2(zp[1], zv0.z, zv0.w);
        PACK2(zp[2], zv1.x, zv1.y); PACK2(zp[3], zv1.z, zv1.w);
        PACK2(zp[4], zv2.x, zv2.y); PACK2(zp[5], zv2.z, zv2.w);
        PACK2(zp[6], zv3.x, zv3.y); PACK2(zp[7], zv3.z, zv3.w);
#pragma unroll
        for (int k = 0; k < 8; ++k) {
            unsigned long long f, g;
            MUL2(f, ep[k], invp);      // f = e * inv
            MUL2(g, rtp, zp[k]);       // g = rt * z
            FMA2(cp[k], f, cp[k], g);  // c = f*c + g
        }

        // ---- out: rank stores its 64-element chunk (warp 0 only) ----
        if (w == 0) {
            float* orow = out + (size_t)t * SZ;
            if (rank < 4) {
                if ((l >> 3) == rank) {
                    ulonglong2 s0; s0.x = cp[0]; s0.y = cp[1];
                    ulonglong2 s1; s1.x = cp[2]; s1.y = cp[3];
                    *(ulonglong2*)(orow + 8 * l)     = s0;
                    *(ulonglong2*)(orow + 8 * l + 4) = s1;
                }
            } else {
                if ((l >> 3) == rank - 4) {
                    ulonglong2 s0; s0.x = cp[4]; s0.y = cp[5];
                    ulonglong2 s1; s1.x = cp[6]; s1.y = cp[7];
                    *(ulonglong2*)(orow + 256 + 8 * l)     = s0;
                    *(ulonglong2*)(orow + 256 + 8 * l + 4) = s1;
                }
            }
        }
        // no loop-end sync: c is in registers; smem buffers are ping-ponged
        // and protected by the causal chain through the mbarrier waits.
    }
    CLUSTER_SYNC();   // keep peers' smem alive until all in-flight st.async land
}

// ---------------------------------------------------------------------------
// launch
// ---------------------------------------------------------------------------
extern "C" void kernel_launch(void* const* d_in, const int* in_sizes, int n_in,
                              void* d_out, int out_size)
{
    const float* x1   = (const float*)d_in[0];
    const float* x2   = (const float*)d_in[1];
    const float* ctx0 = (const float*)d_in[2];
    const float* Wl   = (const float*)d_in[3];
    const float* bl   = (const float*)d_in[4];
    const float* We   = (const float*)d_in[5];
    const float* Wr   = (const float*)d_in[6];
    const float* Wf   = (const float*)d_in[7];
    float* out = (float*)d_out;

    gemm1_kernel<<<dim3(HIDN / 128, TT / 128), 256>>>(x1, x2, Wl, bl);
    gemm2_kernel<<<dim3(SZ / 128, TT / 128), 256>>>(We);
    rate_kernel<<<TT / 4, 128>>>(Wr);
    scan_kernel<<<CLUSTER_N, 256>>>(Wf, ctx0, out);
}